// round 17
// baseline (speedup 1.0000x reference)
#include <cuda_runtime.h>
#include <math.h>

#define BB 8
#define TT 8192
#define DV 1024
#define DQ 768
#define KREP 6
#define NH 8
#define HD 128
#define CC 18
#define FB 444          // k_front blocks (3 per SM)
#define FW (FB * 16)    // k_front total warps
#define PB 148          // k_post blocks: 1/SM (192KB smem)
#define PTHR 512
#define PSMEM (48 * DV * 4)   // 192KB dynamic smem

typedef unsigned long long ull;

// ---------------- scratch (no allocations allowed) ----------------
__device__ __align__(16) float g_pre[2 * BB * DV];
__device__ __align__(16) float g_h[2 * BB * DV];
__device__ __align__(16) float g_mu[BB * DV];
__device__ __align__(16) float g_isg[BB * DV];
__device__ __align__(16) float g_rep[BB * KREP * DV];
__device__ __align__(16) float g_qkv[BB * KREP * 3 * DV];
__device__ __align__(16) float g_ao[BB * KREP * DV];
__device__ float g_attnw[BB * NH * KREP * KREP];
__device__ unsigned g_cnt = 0, g_gen = 0;

__device__ __forceinline__ float warp_sum(float v) {
#pragma unroll
    for (int o = 16; o; o >>= 1) v += __shfl_xor_sync(0xffffffffu, v, o);
    return v;
}

__device__ __forceinline__ ull pack2(float a, float b) {
    ull r;
    asm("mov.b64 %0, {%1, %2};" : "=l"(r) : "f"(a), "f"(b));
    return r;
}
__device__ __forceinline__ ull fma2(ull a, ull b, ull c) {
    ull d;
    asm("fma.rn.f32x2 %0, %1, %2, %3;" : "=l"(d) : "l"(a), "l"(b), "l"(c));
    return d;
}
__device__ __forceinline__ void unpack2(ull v, float& lo, float& hi) {
    asm("mov.b64 {%0, %1}, %2;" : "=f"(lo), "=f"(hi) : "l"(v));
}

// software grid barrier: nblk blocks, all co-resident
__device__ __forceinline__ void gbar(unsigned nblk) {
    __syncthreads();
    if (threadIdx.x == 0) {
        volatile unsigned* vgen = &g_gen;
        unsigned gen = *vgen;
        __threadfence();
        unsigned t = atomicAdd(&g_cnt, 1u);
        if (t == nblk - 1) {
            atomicExch(&g_cnt, 0u);
            __threadfence();
            atomicAdd(&g_gen, 1u);
        } else {
            while (*vgen == gen) { }
            __threadfence();
        }
    }
    __syncthreads();
}

// 512-thread radix-select pass, 2048 bins (verified in R7 mega-kernel)
__device__ void radix512(const unsigned* __restrict__ keys,
                         int shift, int bits, bool first,
                         unsigned* hist, unsigned* wsum, unsigned* wpfx,
                         unsigned* sh_prefix, int* sh_k) {
    int tid = threadIdx.x, lane = tid & 31, wid = tid >> 5;
#pragma unroll
    for (int j = 0; j < 4; j++) hist[tid + j * 512] = 0u;
    __syncthreads();
    unsigned pfx = *sh_prefix;
    unsigned mask = (1u << bits) - 1u;
#pragma unroll
    for (int r = 0; r < 16; r++) {
        unsigned key = keys[tid + r * 512];
        bool ok = first || ((key >> (shift + bits)) == pfx);
        if (ok) atomicAdd(&hist[(key >> shift) & mask], 1u);
    }
    __syncthreads();
    unsigned s0 = hist[tid * 4], s1 = hist[tid * 4 + 1],
             s2 = hist[tid * 4 + 2], s3 = hist[tid * 4 + 3];
    unsigned s = s0 + s1 + s2 + s3;
    unsigned inc = s;
#pragma unroll
    for (int o = 1; o < 32; o <<= 1) {
        unsigned n = __shfl_up_sync(0xffffffffu, inc, o);
        if (lane >= o) inc += n;
    }
    if (lane == 31) wsum[wid] = inc;   // 16 warps
    __syncthreads();
    if (wid == 0) {
        unsigned v = (lane < 16) ? wsum[lane] : 0u;
        unsigned iw = v;
#pragma unroll
        for (int o = 1; o < 32; o <<= 1) {
            unsigned n = __shfl_up_sync(0xffffffffu, iw, o);
            if (lane >= o) iw += n;
        }
        wpfx[lane] = iw - v;
    }
    __syncthreads();
    unsigned base = wpfx[wid] + (inc - s);
    unsigned k = (unsigned)*sh_k;
    if (k >= base && k < base + s) {   // exactly one thread
        int bin = tid * 4;
        unsigned off = base;
        if (k >= off + s0) { off += s0; bin++;
            if (k >= off + s1) { off += s1; bin++;
                if (k >= off + s2) { off += s2; bin++; } } }
        *sh_prefix = (pfx << bits) | (unsigned)bin;
        *sh_k = (int)(k - off);
    }
    __syncthreads();
}

// ===== kernel 1: FRONT — mlp -> LN -> lin2 -> dist -> select, persistent 444x512 =====
__global__ __launch_bounds__(512, 3) void k_front(
    const float* __restrict__ vf, const float* __restrict__ qe,
    const float* __restrict__ mu_w1, const float* __restrict__ mu_b1,
    const float* __restrict__ mu_g,  const float* __restrict__ mu_bt,
    const float* __restrict__ mu_w2, const float* __restrict__ mu_b2,
    const float* __restrict__ sg_w1, const float* __restrict__ sg_b1,
    const float* __restrict__ sg_g,  const float* __restrict__ sg_bt,
    const float* __restrict__ sg_w2, const float* __restrict__ sg_b2,
    float* __restrict__ o_dist, float* __restrict__ o_idx,
    float* __restrict__ o_mu, float* __restrict__ o_sg) {

    __shared__ __align__(16) unsigned char SB[41616];   // keys/hist or mus/iss overlay
    __shared__ float red[16];
    __shared__ float sh_mean, sh_rstd;
    __shared__ unsigned sh_prefix;
    __shared__ int sh_k, sh_nless, sh_neq;
    __shared__ int sels[KREP];

    int tid = threadIdx.x, lane = tid & 31, wid = tid >> 5, blk = blockIdx.x;
    int gw = blk * 16 + wid;

    // ---- P0: Linear(768->1024) both branches: 16384 dots ----
    for (int idx = gw; idx < 16384; idx += FW) {
        int br = idx >> 13;
        int rem = idx & 8191;
        int b = rem >> 10, o = rem & 1023;
        const float* w1 = br ? sg_w1 : mu_w1;
        const float* b1 = br ? sg_b1 : mu_b1;
        const float* x = qe + b * DQ;
        const float* wr = w1 + o * DQ;
        float acc = 0.f;
#pragma unroll
        for (int i = lane; i < DQ; i += 32) acc += wr[i] * x[i];
        acc = warp_sum(acc);
        if (lane == 0) g_pre[(br * BB + b) * DV + o] = acc + b1[o];
    }
    gbar(FB);

    // ---- P1: LayerNorm + ReLU (blocks 0..15) ----
    if (blk < 16) {
        int b = blk >> 1, br = blk & 1;
        const float* src = g_pre + (br * BB + b) * DV;
        float v0 = src[tid], v1 = src[tid + 512];
        float s = warp_sum(v0 + v1);
        if (lane == 0) red[wid] = s;
        __syncthreads();
        if (tid == 0) {
            float m = 0.f;
            for (int i = 0; i < 16; i++) m += red[i];
            sh_mean = m / (float)DV;
        }
        __syncthreads();
        float m = sh_mean;
        float d0 = v0 - m, d1 = v1 - m;
        float vv = warp_sum(d0 * d0 + d1 * d1);
        if (lane == 0) red[wid] = vv;
        __syncthreads();
        if (tid == 0) {
            float q = 0.f;
            for (int i = 0; i < 16; i++) q += red[i];
            sh_rstd = rsqrtf(q / (float)DV + 1e-5f);
        }
        __syncthreads();
        float rstd = sh_rstd;
        const float* g  = br ? sg_g  : mu_g;
        const float* bt = br ? sg_bt : mu_bt;
        float* dst = g_h + (br * BB + b) * DV;
        dst[tid]       = fmaxf(d0 * rstd * g[tid]       + bt[tid], 0.f);
        dst[tid + 512] = fmaxf(d1 * rstd * g[tid + 512] + bt[tid + 512], 0.f);
    }
    gbar(FB);

    // ---- P2: Linear(1024->1024) + mu/softplus epilogue ----
    for (int idx = gw; idx < 16384; idx += FW) {
        int br = idx >> 13;
        int rem = idx & 8191;
        int b = rem >> 10, o = rem & 1023;
        const float* w2 = br ? sg_w2 : mu_w2;
        const float* b2 = br ? sg_b2 : mu_b2;
        const float* x = g_h + (br * BB + b) * DV;
        const float* wr = w2 + o * DV;
        float acc = 0.f;
#pragma unroll
        for (int i = lane; i < DV; i += 32) acc += wr[i] * x[i];
        acc = warp_sum(acc);
        if (lane == 0) {
            float val = acc + b2[o];
            if (br == 0) {
                g_mu[b * DV + o] = val;
                o_mu[b * DV + o] = val;
            } else {
                float sp = fmaxf(val, 0.f) + log1pf(expf(-fabsf(val)));
                float sg = sp + 1e-6f;
                o_sg[b * DV + o] = sg;
                g_isg[b * DV + o] = 1.f / sg;
            }
        }
    }
    gbar(FB);

    // ---- P3: Mahalanobis distance (proven 2-row/warp body), task loop ----
    {
        float4* mus = (float4*)SB;            // 256 float4
        float4* iss = (float4*)(SB + 4096);   // 256 float4
        for (int task = blk; task < 2048; task += FB) {
            int b = task >> 8, chunk = task & 255;
            __syncthreads();
            if (tid < 256) mus[tid] = ((const float4*)(g_mu + b * DV))[tid];
            else           iss[tid - 256] = ((const float4*)(g_isg + b * DV))[tid - 256];
            __syncthreads();
            int t0 = chunk * 32 + wid * 2;
            const float4* v0 = (const float4*)(vf + ((size_t)b * TT + t0) * DV);
            const float4* v1 = v0 + DV / 4;
            float a0 = 0.f, a1 = 0.f;
#pragma unroll
            for (int it = 0; it < 8; it++) {
                int i = lane + it * 32;
                float4 x0 = v0[i], x1 = v1[i], mm = mus[i], ss = iss[i];
                float d;
                d = x0.x - mm.x; a0 += d * d * ss.x;
                d = x0.y - mm.y; a0 += d * d * ss.y;
                d = x0.z - mm.z; a0 += d * d * ss.z;
                d = x0.w - mm.w; a0 += d * d * ss.w;
                d = x1.x - mm.x; a1 += d * d * ss.x;
                d = x1.y - mm.y; a1 += d * d * ss.y;
                d = x1.z - mm.z; a1 += d * d * ss.z;
                d = x1.w - mm.w; a1 += d * d * ss.w;
            }
            a0 = warp_sum(a0);
            a1 = warp_sum(a1);
            if (lane == 0) {
                o_dist[b * TT + t0]     = a0;
                o_dist[b * TT + t0 + 1] = a1;
            }
        }
    }
    gbar(FB);

    // ---- P4: median + top-18 + diversify + gather (blocks 0..7); others exit ----
    if (blk >= BB) return;
    {
        unsigned* keys = (unsigned*)SB;                       // 8192 (32KB)
        unsigned* hist = (unsigned*)(SB + 32768);             // 2048 (8KB)
        unsigned* wsum = (unsigned*)(SB + 40960);             // 32
        unsigned* wpfx = (unsigned*)(SB + 41088);             // 32
        ull* lessK = (ull*)(SB + 41216);                      // 18
        int* eqIdx = (int*)(SB + 41360);                      // 64
        int b = blk;
        const float* drow = o_dist + b * TT;

#pragma unroll
        for (int r = 0; r < 16; r++)
            keys[tid + r * 512] = __float_as_uint(drow[tid + r * 512]);
        if (tid == 0) { sh_prefix = 0u; sh_k = (TT - 1) / 2; }
        __syncthreads();

        radix512(keys, 21, 11, true,  hist, wsum, wpfx, &sh_prefix, &sh_k);
        radix512(keys, 10, 11, false, hist, wsum, wpfx, &sh_prefix, &sh_k);
        radix512(keys,  0, 10, false, hist, wsum, wpfx, &sh_prefix, &sh_k);
        float med = __uint_as_float(sh_prefix);
        __syncthreads();

#pragma unroll
        for (int r = 0; r < 16; r++) {
            int i = tid + r * 512;
            keys[i] = __float_as_uint(fabsf(__uint_as_float(keys[i]) - med));
        }
        if (tid == 0) { sh_prefix = 0u; sh_k = CC - 1; sh_nless = 0; sh_neq = 0; }
        __syncthreads();

        radix512(keys, 21, 11, true,  hist, wsum, wpfx, &sh_prefix, &sh_k);
        radix512(keys, 10, 11, false, hist, wsum, wpfx, &sh_prefix, &sh_k);
        radix512(keys,  0, 10, false, hist, wsum, wpfx, &sh_prefix, &sh_k);
        unsigned vstar = sh_prefix;
        int n_eq_take = sh_k + 1;
        __syncthreads();

#pragma unroll
        for (int r = 0; r < 16; r++) {
            int i = tid + r * 512;
            unsigned key = keys[i];
            if (key < vstar) {
                int p = atomicAdd(&sh_nless, 1);
                lessK[p] = ((ull)key << 13) | (unsigned)i;
            } else if (key == vstar) {
                int p = atomicAdd(&sh_neq, 1);
                if (p < 64) eqIdx[p] = i;
            }
        }
        __syncthreads();

        if (tid == 0) {
            int nless = sh_nless;
            int neq = sh_neq < 64 ? sh_neq : 64;
            for (int i = 1; i < nless; i++) {
                ull kv = lessK[i];
                int j = i - 1;
                while (j >= 0 && lessK[j] > kv) { lessK[j + 1] = lessK[j]; j--; }
                lessK[j + 1] = kv;
            }
            for (int i = 1; i < neq; i++) {
                int kv = eqIdx[i];
                int j = i - 1;
                while (j >= 0 && eqIdx[j] > kv) { eqIdx[j + 1] = eqIdx[j]; j--; }
                eqIdx[j + 1] = kv;
            }
            int cand[CC];
            for (int c = 0; c < nless; c++) cand[c] = (int)(lessK[c] & 0x1FFFull);
            for (int c = 0; c < n_eq_take && nless + c < CC; c++) cand[nless + c] = eqIdx[c];

            const float NINF = __int_as_float(0xff800000);
            float candf[CC], mind[CC];
            int sel[KREP];
            for (int c = 0; c < CC; c++) candf[c] = (float)cand[c];
            for (int c = 0; c < CC; c++) mind[c] = fabsf(candf[c] - candf[0]);
            mind[0] = NINF;
            sel[0] = cand[0];
            for (int sI = 1; sI < KREP; sI++) {
                int best = 0;
                float bm = NINF;
                for (int c = 0; c < CC; c++)
                    if (mind[c] > bm) { bm = mind[c]; best = c; }
                sel[sI] = cand[best];
                float cb = candf[best];
                for (int c = 0; c < CC; c++) mind[c] = fminf(mind[c], fabsf(candf[c] - cb));
                mind[best] = NINF;
            }
            for (int sI = 0; sI < KREP; sI++) {
                sels[sI] = sel[sI];
                o_idx[b * KREP + sI] = (float)sel[sI];
            }
        }
        __syncthreads();

        for (int kk = 0; kk < KREP; kk++) {
            int t = sels[kk];
            const float* src = vf + ((size_t)b * TT + t) * DV;
            float* dst = g_rep + (b * KREP + kk) * DV;
            for (int i = tid; i < DV; i += 512) dst[i] = src[i];
        }
    }
}

// ================= kernel 2: post — row-pair f32x2 GEMM, 4 outputs x 4 pairs ==========
__device__ void gemm_phase2(const float4* __restrict__ xs4, const float* __restrict__ w,
                            const float* __restrict__ bias, float* __restrict__ out,
                            int ostride, int nout) {
    int tid = threadIdx.x, lane = tid & 31, wid = tid >> 5;
    int og_count = nout >> 2;
    int ntask = og_count * 6;                  // 6 chunks of 4 row-pairs
    int gw = blockIdx.x * (PTHR / 32) + wid;
    const ulonglong2* xsu2 = (const ulonglong2*)xs4;
    for (int task = gw; task < ntask; task += PB * (PTHR / 32)) {
        int og = task % og_count, rch = task / og_count;
        int o0 = og * 4, pbase = rch * 4;
        const float2* wp[4];
#pragma unroll
        for (int j = 0; j < 4; j++) wp[j] = (const float2*)(w + (size_t)(o0 + j) * DV);

        ull acc[4][4];
#pragma unroll
        for (int j = 0; j < 4; j++)
#pragma unroll
            for (int p = 0; p < 4; p++) acc[j][p] = 0ull;

        float2 wa[4], wb[4];
#pragma unroll
        for (int j = 0; j < 4; j++) { wa[j] = wp[j][lane]; wb[j] = wp[j][32 + lane]; }
#pragma unroll
        for (int kc = 0; kc < 8; kc++) {
            float2 na[4], nb[4];
            if (kc < 7) {
#pragma unroll
                for (int j = 0; j < 4; j++) {
                    na[j] = wp[j][(kc + 1) * 64 + lane];
                    nb[j] = wp[j][(kc + 1) * 64 + 32 + lane];
                }
            }
            ull wA0[4], wA1[4], wB0[4], wB1[4];
#pragma unroll
            for (int j = 0; j < 4; j++) {
                wA0[j] = pack2(wa[j].x, wa[j].x);
                wA1[j] = pack2(wa[j].y, wa[j].y);
                wB0[j] = pack2(wb[j].x, wb[j].x);
                wB1[j] = pack2(wb[j].y, wb[j].y);
            }
            const ulonglong2* xb = xsu2 + (size_t)pbase * 512 + kc * 64 + lane;
#pragma unroll
            for (int p = 0; p < 4; p++) {
                ulonglong2 ua = xb[(size_t)p * 512];
                ulonglong2 ub = xb[(size_t)p * 512 + 32];
#pragma unroll
                for (int j = 0; j < 4; j++) {
                    acc[j][p] = fma2(ua.x, wA0[j], acc[j][p]);
                    acc[j][p] = fma2(ua.y, wA1[j], acc[j][p]);
                    acc[j][p] = fma2(ub.x, wB0[j], acc[j][p]);
                    acc[j][p] = fma2(ub.y, wB1[j], acc[j][p]);
                }
            }
            if (kc < 7) {
#pragma unroll
                for (int j = 0; j < 4; j++) { wa[j] = na[j]; wb[j] = nb[j]; }
            }
        }
        float bs[4];
#pragma unroll
        for (int j = 0; j < 4; j++) bs[j] = bias[o0 + j];
#pragma unroll
        for (int p = 0; p < 4; p++) {
#pragma unroll
            for (int j = 0; j < 4; j++) {
                float e, o;
                unpack2(acc[j][p], e, o);
                e = warp_sum(e);
                o = warp_sum(o);
                if (lane == p * 4 + j) {
                    int rowe = 2 * (pbase + p);
                    float* de = out + (size_t)rowe * ostride + o0 + j;
                    de[0] = e + bs[j];
                    de[ostride] = o + bs[j];
                }
            }
        }
    }
}

__device__ void stage_pairs(const float* __restrict__ x, float4* __restrict__ xs4) {
    int tid = threadIdx.x;
#pragma unroll
    for (int j = 0; j < 24; j++) {
        int idx = tid + j * PTHR;
        int p = idx >> 9, k2 = idx & 511;
        float2 e2 = ((const float2*)x)[(size_t)(2 * p) * 512 + k2];
        float2 o2 = ((const float2*)x)[(size_t)(2 * p + 1) * 512 + k2];
        xs4[idx] = make_float4(e2.x, o2.x, e2.y, o2.y);
    }
}

__global__ __launch_bounds__(PTHR, 1) void k_post(
    const float* __restrict__ in_w,  const float* __restrict__ in_b,
    const float* __restrict__ out_w, const float* __restrict__ out_b,
    float* __restrict__ o_ref, float* __restrict__ o_attn) {

    extern __shared__ __align__(16) float sdyn[];   // 192KB
    float4* xs4 = (float4*)sdyn;
    int tid = threadIdx.x, lane = tid & 31, wid = tid >> 5, blk = blockIdx.x;

    stage_pairs(g_rep, xs4);
    __syncthreads();

    gemm_phase2(xs4, in_w, in_b, g_qkv, 3 * DV, 3 * DV);
    gbar(PB);

    if (blk < BB * NH) {
        int b = blk >> 3, h = blk & 7;
        float* qs = sdyn;
        float* ks = sdyn + KREP * HD;
        float* vs = sdyn + 2 * KREP * HD;
        for (int i = tid; i < KREP * HD; i += PTHR) {
            int row = i >> 7, d = i & 127;
            const float* base = g_qkv + (b * KREP + row) * 3 * DV + h * HD + d;
            qs[i] = base[0];
            ks[i] = base[DV];
            vs[i] = base[2 * DV];
        }
        __syncthreads();
        if (wid < KREP) {
            int i = wid;
            float sc[KREP];
            const float scale = 0.08838834764831845f;  // 1/sqrt(128)
            for (int j = 0; j < KREP; j++) {
                float acc = 0.f;
#pragma unroll
                for (int m = 0; m < 4; m++)
                    acc += qs[i * HD + lane + 32 * m] * ks[j * HD + lane + 32 * m];
                acc = warp_sum(acc);
                sc[j] = acc * scale;
            }
            float mx = sc[0];
            for (int j = 1; j < KREP; j++) mx = fmaxf(mx, sc[j]);
            float den = 0.f;
            for (int j = 0; j < KREP; j++) { sc[j] = expf(sc[j] - mx); den += sc[j]; }
            float rden = 1.f / den;
            for (int j = 0; j < KREP; j++) sc[j] *= rden;
            if (lane < KREP)
                g_attnw[((b * NH + h) * KREP + i) * KREP + lane] = sc[lane];
            for (int d = lane; d < HD; d += 32) {
                float o = 0.f;
                for (int j = 0; j < KREP; j++) o += sc[j] * vs[j * HD + d];
                g_ao[(b * KREP + i) * DV + h * HD + d] = o;
            }
        }
    }
    gbar(PB);

    if (blk >= 64 && blk < 64 + BB && tid < KREP * KREP) {
        int b = blk - 64;
        float s = 0.f;
        for (int h = 0; h < NH; h++) s += g_attnw[(b * NH + h) * KREP * KREP + tid];
        o_attn[b * KREP * KREP + tid] = s * (1.f / (float)NH);
    }
    __syncthreads();
    stage_pairs(g_ao, xs4);
    __syncthreads();
    gemm_phase2(xs4, out_w, out_b, o_ref, DV, DV);
}

// ---------------- launcher: TWO kernels ----------------
extern "C" void kernel_launch(void* const* d_in, const int* in_sizes, int n_in,
                              void* d_out, int out_size) {
    const float* vf    = (const float*)d_in[0];
    const float* qe    = (const float*)d_in[1];
    const float* mu_w1 = (const float*)d_in[2];
    const float* mu_b1 = (const float*)d_in[3];
    const float* mu_g  = (const float*)d_in[4];
    const float* mu_bt = (const float*)d_in[5];
    const float* mu_w2 = (const float*)d_in[6];
    const float* mu_b2 = (const float*)d_in[7];
    const float* sg_w1 = (const float*)d_in[8];
    const float* sg_b1 = (const float*)d_in[9];
    const float* sg_g  = (const float*)d_in[10];
    const float* sg_bt = (const float*)d_in[11];
    const float* sg_w2 = (const float*)d_in[12];
    const float* sg_b2 = (const float*)d_in[13];
    const float* in_w  = (const float*)d_in[14];
    const float* in_b  = (const float*)d_in[15];
    const float* out_w = (const float*)d_in[16];
    const float* out_b = (const float*)d_in[17];

    float* out = (float*)d_out;
    float* o_ref  = out;           // [8,6,1024]  49152
    float* o_idx  = out + 49152;   // [8,6]       48
    float* o_dist = out + 49200;   // [8,8192]    65536
    float* o_mu   = out + 114736;  // [8,1024]    8192
    float* o_sg   = out + 122928;  // [8,1024]    8192
    float* o_attn = out + 131120;  // [8,6,6]     288

    static int attr_set = 0;
    if (!attr_set) {
        cudaFuncSetAttribute(k_post, cudaFuncAttributeMaxDynamicSharedMemorySize, PSMEM);
        attr_set = 1;
    }

    k_front<<<FB, 512>>>(vf, qe, mu_w1, mu_b1, mu_g, mu_bt, mu_w2, mu_b2,
                         sg_w1, sg_b1, sg_g, sg_bt, sg_w2, sg_b2,
                         o_dist, o_idx, o_mu, o_sg);
    k_post<<<PB, PTHR, PSMEM>>>(in_w, in_b, out_w, out_b, o_ref, o_attn);
}